// round 14
// baseline (speedup 1.0000x reference)
#include <cuda_runtime.h>
#include <cuda_fp16.h>
#include <cstddef>

#define NN 50000
#define EE 800000
#define ET (EE + NN + 32)
#define BB 50
#define FIN 16
#define HIDC 64
#define EDGE_BLOCKS ((EE + 255) / 256)
#define PREPB 196

// ------------------------- device scratch (static, zero-initialized at load) -------------------------
__device__ float  g_ew[EE];
__device__ int    g_erank[EE];        // edge rank within dst segment (from histogram atomic)
__device__ float  g_ewpart[EDGE_BLOCKS];
__device__ float  g_ew_mean;
__device__ int    g_deg[NN];          // zero at load; re-zeroed by k_scan3cs each run
__device__ int    g_off[NN + 1];
__device__ int    g_bsum[64];
__device__ int    g_done;             // zero at load; reset by last block each run
__device__ int2   g_csr[ET];          // (src, ew bits)
__device__ float  g_y[(size_t)NN * 64];
__device__ __half g_h[(size_t)NN * 256];
__device__ float  g_x0[NN * HIDC];
__device__ float  g_x1[NN * HIDC];
__device__ float  g_as[NN * 4];
__device__ float  g_ad[NN * 4];
__device__ float  g_vs2[256], g_vd2[256], g_vs3[256], g_vd3[256];
__device__ float  g_ce[12];

__device__ __forceinline__ float elu1(float x)  { return x > 0.f ? x : __expf(x) - 1.f; }
__device__ __forceinline__ float lrelu(float x) { return x > 0.f ? x : 0.2f * x; }

// ------------------------- fused: prep (blocks 0..195) + edge MLP/histogram+rank (rest) -------------------------
__global__ void __launch_bounds__(256) k_prep_edge(
    const float* __restrict__ x, const float* __restrict__ W1, const float* __restrict__ Ws,
    const float* __restrict__ att_s, const float* __restrict__ att_d,
    const float* __restrict__ We, const float* __restrict__ att_e,
    const float* __restrict__ ea, const int* __restrict__ dst,
    const float* __restrict__ w1, const float* __restrict__ b1,
    const float* __restrict__ w2, const float* __restrict__ b2)
{
    int t = threadIdx.x;
    if (blockIdx.x < PREPB) {
        // ---- node prep: conv1 alphas + fold vectors ----
        __shared__ float svs[64], svd[64];
        if (t < 64) {
            int k = t >> 2, h = t & 3;
            float s = 0.f;
            for (int c = 0; c < 64; c++) s += W1[k * 256 + h * 64 + c] * att_s[h * 64 + c];
            svs[t] = s;
        } else if (t < 128) {
            int u = t - 64;
            int k = u >> 2, h = u & 3;
            float d = 0.f;
            for (int c = 0; c < 64; c++) d += W1[k * 256 + h * 64 + c] * att_d[h * 64 + c];
            svd[u] = d;
        }
        __syncthreads();

        int node = blockIdx.x * 256 + t;
        if (node < NN) {
            float xr[16];
            const float4* xp = (const float4*)(x + node * 16);
            #pragma unroll
            for (int q = 0; q < 4; q++) {
                float4 v = xp[q];
                xr[4*q] = v.x; xr[4*q+1] = v.y; xr[4*q+2] = v.z; xr[4*q+3] = v.w;
            }
            #pragma unroll
            for (int h = 0; h < 4; h++) {
                float a = 0.f, d = 0.f;
                #pragma unroll
                for (int k = 0; k < 16; k++) {
                    a += xr[k] * svs[k * 4 + h];
                    d += xr[k] * svd[k * 4 + h];
                }
                g_as[node * 4 + h] = a;
                g_ad[node * 4 + h] = d;
            }
        }

        if (blockIdx.x == 0) {
            int k = t >> 2, h = t & 3;
            float s2 = 0.f, d2 = 0.f, s3 = 0.f, d3 = 0.f;
            for (int c = 0; c < 64; c++) {
                float w2v = Ws[k * 256 + h * 64 + c];
                float w3v = Ws[16384 + k * 256 + h * 64 + c];
                s2 += w2v * att_s[256 + h * 64 + c];
                d2 += w2v * att_d[256 + h * 64 + c];
                s3 += w3v * att_s[512 + h * 64 + c];
                d3 += w3v * att_d[512 + h * 64 + c];
            }
            g_vs2[t] = s2; g_vd2[t] = d2; g_vs3[t] = s3; g_vd3[t] = d3;
            if (t < 12) {
                int l = t >> 2, hh = t & 3;
                float ce = 0.f;
                for (int c = 0; c < 64; c++) ce += We[l * 256 + hh * 64 + c] * att_e[l * 256 + hh * 64 + c];
                g_ce[t] = ce;
            }
        }
    } else {
        // ---- edge MLP + dst histogram (atomic return = slot rank) ----
        __shared__ float ws[448];
        __shared__ float red[8];
        int eb = blockIdx.x - PREPB;
        for (int i = t; i < 448; i += 256)
            ws[i] = (i < 320) ? w1[i] : (i < 384) ? b1[i - 320] : w2[i - 384];
        __syncthreads();

        int e = eb * 256 + t;
        float val = 0.f;
        if (e < EE) {
            float a0 = ea[e*5+0], a1 = ea[e*5+1], a2 = ea[e*5+2], a3 = ea[e*5+3], a4 = ea[e*5+4];
            float acc = __ldg(b2);
            #pragma unroll 8
            for (int j = 0; j < 64; j++) {
                float tv = ws[320+j] + a0*ws[j] + a1*ws[64+j] + a2*ws[128+j] + a3*ws[192+j] + a4*ws[256+j];
                tv = fmaxf(tv, 0.f);
                acc += tv * ws[384+j];
            }
            val = 1.f / (1.f + __expf(-acc));
            g_ew[e] = val;
            g_erank[e] = atomicAdd(&g_deg[dst[e]], 1);
        }
        float s = val;
        #pragma unroll
        for (int o = 16; o; o >>= 1) s += __shfl_xor_sync(0xffffffffu, s, o);
        if ((t & 31) == 0) red[t >> 5] = s;
        __syncthreads();
        if (t == 0) {
            float tv = 0.f;
            for (int w = 0; w < 8; w++) tv += red[w];
            g_ewpart[eb] = tv;
        }
    }
}

// ------------------------- scan stage 1 + (last block) stage 2 + ew mean -------------------------
__global__ void __launch_bounds__(1024) k_scan12() {
    __shared__ int wsum[32];
    __shared__ int amLast;
    int tid = threadIdx.x, lane = tid & 31, w = tid >> 5;
    int i = blockIdx.x * 1024 + tid;
    int x = (i < NN) ? g_deg[i] + 1 : 0;
    #pragma unroll
    for (int d = 1; d < 32; d <<= 1) {
        int y = __shfl_up_sync(0xffffffffu, x, d);
        if (lane >= d) x += y;
    }
    if (lane == 31) wsum[w] = x;
    __syncthreads();
    if (w == 0) {
        int y = wsum[lane];
        #pragma unroll
        for (int d = 1; d < 32; d <<= 1) {
            int z = __shfl_up_sync(0xffffffffu, y, d);
            if (lane >= d) y += z;
        }
        wsum[lane] = y;
    }
    __syncthreads();
    if (w) x += wsum[w - 1];
    if (i < NN) g_off[i + 1] = x;
    if (tid == 1023) g_bsum[blockIdx.x] = x;

    // last arriving block performs stage 2 (bsum prefix) + ew mean
    __threadfence();
    if (tid == 0) amLast = (atomicAdd(&g_done, 1) == gridDim.x - 1);
    __syncthreads();
    if (!amLast) return;

    __shared__ float red[32];
    float s = 0.f;
    for (int q = tid; q < EDGE_BLOCKS; q += 1024) s += g_ewpart[q];
    #pragma unroll
    for (int o = 16; o; o >>= 1) s += __shfl_xor_sync(0xffffffffu, s, o);
    if (lane == 0) red[w] = s;
    __syncthreads();
    if (tid == 0) {
        float tot = 0.f;
        for (int q = 0; q < 32; q++) tot += red[q];
        g_ew_mean = tot * (1.f / EE);
        int running = 0;
        for (int b = 0; b < 49; b++) { int t2 = g_bsum[b]; g_bsum[b] = running; running += t2; }
        g_done = 0;   // ready for next replay
    }
}

// ------------------------- scan stage 3 + self-loop + deg re-zero -------------------------
__global__ void k_scan3cs() {
    int i = blockIdx.x * 1024 + threadIdx.x;
    if (i < NN) {
        int v = g_off[i + 1] + g_bsum[blockIdx.x];
        g_off[i + 1] = v;
        g_csr[v - 1] = make_int2(i, __float_as_int(g_ew_mean));
        g_deg[i] = 0;                            // ready for next replay
    }
    if (i == 0) g_off[0] = 0;
}

// ------------------------- scatter edges into CSR: NO atomics (rank precomputed), 4 edges/thread -------------------------
__global__ void __launch_bounds__(256) k_scatter(const int* __restrict__ src, const int* __restrict__ dst)
{
    int i4 = blockIdx.x * 256 + threadIdx.x;
    if (i4 >= EE / 4) return;    // EE % 4 == 0
    int4   d4 = ((const int4*)dst)[i4];
    int4   s4 = ((const int4*)src)[i4];
    int4   r4 = ((const int4*)g_erank)[i4];
    float4 w4 = ((const float4*)g_ew)[i4];
    int p0 = g_off[d4.x] + r4.x;
    int p1 = g_off[d4.y] + r4.y;
    int p2 = g_off[d4.z] + r4.z;
    int p3 = g_off[d4.w] + r4.w;
    g_csr[p0] = make_int2(s4.x, __float_as_int(w4.x));
    g_csr[p1] = make_int2(s4.y, __float_as_int(w4.y));
    g_csr[p2] = make_int2(s4.z, __float_as_int(w4.z));
    g_csr[p3] = make_int2(s4.w, __float_as_int(w4.w));
}

// ------------------------- conv1 aggregation (64 B/edge raw-x gather, MLP=4 pipeline) -------------------------
__global__ void __launch_bounds__(256) k_agg1(const float* __restrict__ x)
{
    __shared__ int   s_sm[8][32];
    __shared__ float4 p_sm[8][32];
    const unsigned F = 0xffffffffu;
    int lane = threadIdx.x & 31, w = threadIdx.x >> 5;
    int n = blockIdx.x * 8 + w;
    if (n >= NN) return;

    int start = g_off[n], end = g_off[n + 1];
    float4 adv = *(const float4*)(g_ad + n * 4);
    float ce0 = g_ce[0], ce1 = g_ce[1], ce2 = g_ce[2], ce3 = g_ce[3];
    int head = lane >> 3, kg = lane & 7;

    float a0 = 0.f, a1 = 0.f;
    float sl0 = 0.f, sl1 = 0.f, sl2 = 0.f, sl3 = 0.f;
    const float* pr = (const float*)(p_sm[w]);
    const int* sr = s_sm[w];

    for (int base = start; base < end; base += 32) {
        int i = base + lane;
        bool v = i < end;
        int2 ed = v ? g_csr[i] : make_int2(0, 0);
        int sidx = ed.x;
        float wgt = __int_as_float(ed.y);
        float4 asv = *(const float4*)(g_as + sidx * 4);
        float p0 = v ? __expf(lrelu(asv.x + adv.x + wgt * ce0)) : 0.f;
        float p1 = v ? __expf(lrelu(asv.y + adv.y + wgt * ce1)) : 0.f;
        float p2 = v ? __expf(lrelu(asv.z + adv.z + wgt * ce2)) : 0.f;
        float p3 = v ? __expf(lrelu(asv.w + adv.w + wgt * ce3)) : 0.f;
        sl0 += p0; sl1 += p1; sl2 += p2; sl3 += p3;
        s_sm[w][lane] = sidx;
        p_sm[w][lane] = make_float4(p0, p1, p2, p3);
        __syncwarp();
        int cnt4 = (min(32, end - base) + 3) & ~3;   // padded slots carry p=0 -> contribute 0
        for (int kk = 0; kk < cnt4; kk += 4) {
            int s0 = sr[kk], s1 = sr[kk+1], s2 = sr[kk+2], s3 = sr[kk+3];
            float2 xa = *(const float2*)(x + s0 * 16 + kg * 2);
            float2 xb = *(const float2*)(x + s1 * 16 + kg * 2);
            float2 xc = *(const float2*)(x + s2 * 16 + kg * 2);
            float2 xd = *(const float2*)(x + s3 * 16 + kg * 2);
            float pk0 = pr[kk*4+head], pk1 = pr[(kk+1)*4+head];
            float pk2 = pr[(kk+2)*4+head], pk3 = pr[(kk+3)*4+head];
            a0 += pk0 * xa.x; a1 += pk0 * xa.y;
            a0 += pk1 * xb.x; a1 += pk1 * xb.y;
            a0 += pk2 * xc.x; a1 += pk2 * xc.y;
            a0 += pk3 * xd.x; a1 += pk3 * xd.y;
        }
        __syncwarp();
    }

    #pragma unroll
    for (int o = 16; o; o >>= 1) {
        sl0 += __shfl_xor_sync(F, sl0, o);
        sl1 += __shfl_xor_sync(F, sl1, o);
        sl2 += __shfl_xor_sync(F, sl2, o);
        sl3 += __shfl_xor_sync(F, sl3, o);
    }
    float myS = (lane & 16) ? ((lane & 8) ? sl3 : sl2) : ((lane & 8) ? sl1 : sl0);
    float inv = 1.f / (myS + 1e-16f);
    *(float2*)(g_y + (size_t)n * 64 + head * 16 + kg * 2) = make_float2(a0 * inv, a1 * inv);
}

// ------------------------- fused conv1-post + conv2-GEMM + conv2 alphas (2-way ILP) -------------------------
__global__ void __launch_bounds__(256) k_fused12(
    const float* __restrict__ W1, const float* __restrict__ bias1, const float* __restrict__ Ws)
{
    __shared__ __align__(16) float ys[32 * 64];
    __shared__ __align__(16) float xs[32 * 64];
    int t = threadIdx.x;
    int n0 = blockIdx.x * 32;

    for (int i = t; i < 32 * 64; i += 256) {
        int gi = n0 * 64 + i;
        ys[i] = (gi < NN * 64) ? g_y[gi] : 0.f;
    }
    __syncthreads();

    // Phase A: x0 = elu(Y1 @ W1fold + b), 2 nodes in flight
    {
        int c = t & 63, grp = t >> 6;
        unsigned long long wd[32];
        #pragma unroll
        for (int j2 = 0; j2 < 32; j2++) {
            int j = 2 * j2;
            int k = j & 15, hh = j >> 4;
            float w0 = W1[k * 256 + hh * 64 + c] * 0.25f;
            float w1v = W1[(k + 1) * 256 + hh * 64 + c] * 0.25f;
            asm("mov.b64 %0, {%1, %2};" : "=l"(wd[j2]) : "f"(w0), "f"(w1v));
        }
        float bc = bias1[c];
        for (int nn = grp * 8; nn < grp * 8 + 8; nn += 2) {
            const ulonglong2* ya = (const ulonglong2*)(ys + nn * 64);
            const ulonglong2* yb = (const ulonglong2*)(ys + nn * 64 + 64);
            unsigned long long aa = 0ull, ab = 0ull;
            #pragma unroll
            for (int q = 0; q < 16; q++) {
                ulonglong2 va = ya[q];
                ulonglong2 vb = yb[q];
                asm("fma.rn.f32x2 %0, %1, %2, %0;" : "+l"(aa) : "l"(va.x), "l"(wd[2 * q]));
                asm("fma.rn.f32x2 %0, %1, %2, %0;" : "+l"(ab) : "l"(vb.x), "l"(wd[2 * q]));
                asm("fma.rn.f32x2 %0, %1, %2, %0;" : "+l"(aa) : "l"(va.y), "l"(wd[2 * q + 1]));
                asm("fma.rn.f32x2 %0, %1, %2, %0;" : "+l"(ab) : "l"(vb.y), "l"(wd[2 * q + 1]));
            }
            float lo0, hi0, lo1, hi1;
            asm("mov.b64 {%0, %1}, %2;" : "=f"(lo0), "=f"(hi0) : "l"(aa));
            asm("mov.b64 {%0, %1}, %2;" : "=f"(lo1), "=f"(hi1) : "l"(ab));
            float v0 = elu1(lo0 + hi0 + bc);
            float v1 = elu1(lo1 + hi1 + bc);
            xs[nn * 64 + c] = v0;
            xs[nn * 64 + 64 + c] = v1;
            if (n0 + nn < NN)     g_x0[(n0 + nn) * 64 + c] = v0;
            if (n0 + nn + 1 < NN) g_x0[(n0 + nn + 1) * 64 + c] = v1;
        }
    }
    __syncthreads();

    // Phase B: h2 = x0 @ W2 (fp16 out), 2 nodes in flight
    {
        unsigned long long wd[32];
        #pragma unroll
        for (int k2 = 0; k2 < 32; k2++) {
            float w0 = Ws[(2 * k2) * 256 + t];
            float w1v = Ws[(2 * k2 + 1) * 256 + t];
            asm("mov.b64 %0, {%1, %2};" : "=l"(wd[k2]) : "f"(w0), "f"(w1v));
        }
        for (int nn = 0; nn < 32; nn += 2) {
            const ulonglong2* xa = (const ulonglong2*)(xs + nn * 64);
            const ulonglong2* xb = (const ulonglong2*)(xs + nn * 64 + 64);
            unsigned long long aa = 0ull, ab = 0ull;
            #pragma unroll
            for (int q = 0; q < 16; q++) {
                ulonglong2 va = xa[q];
                ulonglong2 vb = xb[q];
                asm("fma.rn.f32x2 %0, %1, %2, %0;" : "+l"(aa) : "l"(va.x), "l"(wd[2 * q]));
                asm("fma.rn.f32x2 %0, %1, %2, %0;" : "+l"(ab) : "l"(vb.x), "l"(wd[2 * q]));
                asm("fma.rn.f32x2 %0, %1, %2, %0;" : "+l"(aa) : "l"(va.y), "l"(wd[2 * q + 1]));
                asm("fma.rn.f32x2 %0, %1, %2, %0;" : "+l"(ab) : "l"(vb.y), "l"(wd[2 * q + 1]));
            }
            float lo0, hi0, lo1, hi1;
            asm("mov.b64 {%0, %1}, %2;" : "=f"(lo0), "=f"(hi0) : "l"(aa));
            asm("mov.b64 {%0, %1}, %2;" : "=f"(lo1), "=f"(hi1) : "l"(ab));
            if (n0 + nn < NN)     g_h[(size_t)(n0 + nn) * 256 + t]     = __float2half(lo0 + hi0);
            if (n0 + nn + 1 < NN) g_h[(size_t)(n0 + nn + 1) * 256 + t] = __float2half(lo1 + hi1);
        }
    }

    // Phase C: conv2 attention dots (256 slots = 32 nodes x 8 roles)
    {
        int nn = t >> 3, role = t & 7, h = role & 3;
        int node = n0 + nn;
        if (node < NN) {
            const float* vv = (role < 4) ? g_vs2 : g_vd2;
            float a = 0.f;
            #pragma unroll
            for (int k = 0; k < 64; k++) a += xs[nn * 64 + k] * vv[k * 4 + h];
            ((role < 4) ? g_as : g_ad)[node * 4 + h] = a;
        }
    }
}

// ------------------------- conv2 aggregation (512 B/edge fp16 h gather, MLP=4) + residual epilogue -------------------------
__global__ void __launch_bounds__(256) k_agg2(const float* __restrict__ bias)
{
    __shared__ int   s_sm[8][32];
    __shared__ float4 p_sm[8][32];
    const unsigned F = 0xffffffffu;
    int lane = threadIdx.x & 31, w = threadIdx.x >> 5;
    int n = blockIdx.x * 8 + w;
    if (n >= NN) return;

    int start = g_off[n], end = g_off[n + 1];
    float4 adv = *(const float4*)(g_ad + n * 4);
    float ce0 = g_ce[4], ce1 = g_ce[5], ce2 = g_ce[6], ce3 = g_ce[7];
    int head = lane >> 3;

    float sl0 = 0.f, sl1 = 0.f, sl2 = 0.f, sl3 = 0.f;
    float acc[8];
    #pragma unroll
    for (int j = 0; j < 8; j++) acc[j] = 0.f;
    const float* pr = (const float*)(p_sm[w]);
    const int* sr = s_sm[w];

    for (int base = start; base < end; base += 32) {
        int i = base + lane;
        bool v = i < end;
        int2 ed = v ? g_csr[i] : make_int2(0, 0);
        int sidx = ed.x;
        float wgt = __int_as_float(ed.y);
        float4 asv = *(const float4*)(g_as + sidx * 4);
        float p0 = v ? __expf(lrelu(asv.x + adv.x + wgt * ce0)) : 0.f;
        float p1 = v ? __expf(lrelu(asv.y + adv.y + wgt * ce1)) : 0.f;
        float p2 = v ? __expf(lrelu(asv.z + adv.z + wgt * ce2)) : 0.f;
        float p3 = v ? __expf(lrelu(asv.w + adv.w + wgt * ce3)) : 0.f;
        sl0 += p0; sl1 += p1; sl2 += p2; sl3 += p3;
        s_sm[w][lane] = sidx;
        p_sm[w][lane] = make_float4(p0, p1, p2, p3);
        __syncwarp();
        int cnt4 = (min(32, end - base) + 3) & ~3;   // padded slots carry p=0
        for (int kk = 0; kk < cnt4; kk += 4) {
            int s0 = sr[kk], s1 = sr[kk+1], s2 = sr[kk+2], s3 = sr[kk+3];
            uint4 h0 = *(const uint4*)(g_h + ((size_t)s0 << 8) + (lane << 3));
            uint4 h1 = *(const uint4*)(g_h + ((size_t)s1 << 8) + (lane << 3));
            uint4 h2 = *(const uint4*)(g_h + ((size_t)s2 << 8) + (lane << 3));
            uint4 h3 = *(const uint4*)(g_h + ((size_t)s3 << 8) + (lane << 3));
            float pk0 = pr[kk*4+head], pk1 = pr[(kk+1)*4+head];
            float pk2 = pr[(kk+2)*4+head], pk3 = pr[(kk+3)*4+head];
            #pragma unroll
            for (int q = 0; q < 4; q++) {
                float2 f0 = __half22float2(*reinterpret_cast<__half2*>(&(&h0.x)[q]));
                float2 f1 = __half22float2(*reinterpret_cast<__half2*>(&(&h1.x)[q]));
                float2 f2 = __half22float2(*reinterpret_cast<__half2*>(&(&h2.x)[q]));
                float2 f3 = __half22float2(*reinterpret_cast<__half2*>(&(&h3.x)[q]));
                acc[2*q]   += pk0 * f0.x + pk1 * f1.x + pk2 * f2.x + pk3 * f3.x;
                acc[2*q+1] += pk0 * f0.y + pk1 * f1.y + pk2 * f2.y + pk3 * f3.y;
            }
        }
        __syncwarp();
    }

    #pragma unroll
    for (int o = 16; o; o >>= 1) {
        sl0 += __shfl_xor_sync(F, sl0, o);
        sl1 += __shfl_xor_sync(F, sl1, o);
        sl2 += __shfl_xor_sync(F, sl2, o);
        sl3 += __shfl_xor_sync(F, sl3, o);
    }
    float myS = (lane & 16) ? ((lane & 8) ? sl3 : sl2) : ((lane & 8) ? sl1 : sl0);
    float inv = 1.f / (myS + 1e-16f);
    float r[8];
    #pragma unroll
    for (int j = 0; j < 8; j++) {
        float vv = acc[j] * inv;
        vv += __shfl_xor_sync(F, vv, 8);
        vv += __shfl_xor_sync(F, vv, 16);
        r[j] = vv;
    }
    if (lane < 8) {
        float o[8];
        #pragma unroll
        for (int j = 0; j < 8; j++) {
            int c = lane * 8 + j;
            o[j] = elu1(0.25f * r[j] + __ldg(bias + c) + g_x0[(size_t)n * 64 + c]);
        }
        float4* op = (float4*)(g_x1 + (size_t)n * 64 + lane * 8);
        op[0] = make_float4(o[0], o[1], o[2], o[3]);
        op[1] = make_float4(o[4], o[5], o[6], o[7]);
    }
}

// ------------------------- conv3 @ 50 targets + LayerNorm + MLP -------------------------
__global__ void __launch_bounds__(128) k_final3(
    const int* __restrict__ batch, const float* __restrict__ Ws3, const float* __restrict__ bias3,
    const float* __restrict__ lng, const float* __restrict__ lnb,
    const float* __restrict__ l1w, const float* __restrict__ l1b,
    const float* __restrict__ l2w, const float* __restrict__ l2b,
    float* __restrict__ out)
{
    __shared__ float xnode[64];
    __shared__ float adsh[4];
    __shared__ float ysh[4][4][64];
    __shared__ float ssh[4][4];
    __shared__ float Y[4][64];
    __shared__ float pt[128];
    __shared__ float xbuf[64], tbuf[64];
    const unsigned F = 0xffffffffu;
    int t = threadIdx.x, lane = t & 31, w = t >> 5;
    int b = blockIdx.x;

    int lo = 0, hi = NN;
    while (lo < hi) {
        int mid = (lo + hi) >> 1;
        if (batch[mid] < b) lo = mid + 1; else hi = mid;
    }
    int n = lo;

    if (t < 64) xnode[t] = g_x1[(size_t)n * 64 + t];
    __syncthreads();
    if (t < 4) {
        float a = 0.f;
        #pragma unroll
        for (int k = 0; k < 64; k++) a += xnode[k] * g_vd3[k * 4 + t];
        adsh[t] = a;
    }
    __syncthreads();

    float4 adv = make_float4(adsh[0], adsh[1], adsh[2], adsh[3]);
    float ce0 = g_ce[8], ce1 = g_ce[9], ce2 = g_ce[10], ce3 = g_ce[11];
    int start = g_off[n], len = g_off[n + 1] - start;

    float4 v0 = *(const float4*)(g_vs3 + lane * 8);
    float4 v1 = *(const float4*)(g_vs3 + lane * 8 + 4);

    float yk[8];
    #pragma unroll
    for (int j = 0; j < 8; j++) yk[j] = 0.f;
    float sw0 = 0.f, sw1 = 0.f, sw2 = 0.f, sw3 = 0.f;

    for (int j = w; j < len; j += 4) {
        int2 ed = g_csr[start + j];
        int s = ed.x;
        float wgt = __int_as_float(ed.y);
        float2 xs = *(const float2*)(g_x1 + (size_t)s * 64 + lane * 2);
        float d0 = xs.x * v0.x + xs.y * v1.x;
        float d1 = xs.x * v0.y + xs.y * v1.y;
        float d2 = xs.x * v0.z + xs.y * v1.z;
        float d3 = xs.x * v0.w + xs.y * v1.w;
        #pragma unroll
        for (int o = 16; o; o >>= 1) {
            d0 += __shfl_xor_sync(F, d0, o);
            d1 += __shfl_xor_sync(F, d1, o);
            d2 += __shfl_xor_sync(F, d2, o);
            d3 += __shfl_xor_sync(F, d3, o);
        }
        float p0 = __expf(lrelu(d0 + adv.x + wgt * ce0));
        float p1 = __expf(lrelu(d1 + adv.y + wgt * ce1));
        float p2 = __expf(lrelu(d2 + adv.z + wgt * ce2));
        float p3 = __expf(lrelu(d3 + adv.w + wgt * ce3));
        sw0 += p0; sw1 += p1; sw2 += p2; sw3 += p3;
        yk[0] += p0 * xs.x; yk[1] += p0 * xs.y;
        yk[2] += p1 * xs.x; yk[3] += p1 * xs.y;
        yk[4] += p2 * xs.x; yk[5] += p2 * xs.y;
        yk[6] += p3 * xs.x; yk[7] += p3 * xs.y;
    }
    #pragma unroll
    for (int h = 0; h < 4; h++) {
        ysh[w][h][lane * 2]     = yk[h * 2];
        ysh[w][h][lane * 2 + 1] = yk[h * 2 + 1];
    }
    if (lane == 0) { ssh[w][0] = sw0; ssh[w][1] = sw1; ssh[w][2] = sw2; ssh[w][3] = sw3; }
    __syncthreads();

    #pragma unroll
    for (int r = 0; r < 2; r++) {
        int idx = t + r * 128;
        int h = idx >> 6, k = idx & 63;
        float v = ysh[0][h][k] + ysh[1][h][k] + ysh[2][h][k] + ysh[3][h][k];
        float sh = ssh[0][h] + ssh[1][h] + ssh[2][h] + ssh[3][h];
        Y[h][k] = v / (sh + 1e-16f);
    }
    __syncthreads();

    int c = t & 63, half = t >> 6;
    float a = 0.f;
    #pragma unroll
    for (int hh = 0; hh < 2; hh++) {
        int h = half * 2 + hh;
        for (int k = 0; k < 64; k++) a += Y[h][k] * __ldg(Ws3 + k * 256 + h * 64 + c);
    }
    pt[t] = a;
    __syncthreads();
    if (t < 64) xbuf[t] = elu1(0.25f * (pt[t] + pt[t + 64]) + bias3[t] + xnode[t]);
    __syncthreads();

    if (w == 0) {
        float v0l = xbuf[lane], v1l = xbuf[lane + 32];
        float sum = v0l + v1l;
        #pragma unroll
        for (int o = 16; o; o >>= 1) sum += __shfl_xor_sync(F, sum, o);
        float mean = sum * (1.f / 64.f);
        float dd0 = v0l - mean, dd1 = v1l - mean;
        float vs = dd0 * dd0 + dd1 * dd1;
        #pragma unroll
        for (int o = 16; o; o >>= 1) vs += __shfl_xor_sync(F, vs, o);
        float rstd = rsqrtf(vs * (1.f / 64.f) + 1e-5f);
        xbuf[lane]      = dd0 * rstd * lng[lane]      + lnb[lane];
        xbuf[lane + 32] = dd1 * rstd * lng[lane + 32] + lnb[lane + 32];
        __syncwarp();

        float a0 = l1b[lane], a1 = l1b[lane + 32];
        for (int cc = 0; cc < 64; cc++) {
            float xv = xbuf[cc];
            a0 += xv * l1w[cc * 64 + lane];
            a1 += xv * l1w[cc * 64 + lane + 32];
        }
        tbuf[lane]      = elu1(a0);
        tbuf[lane + 32] = elu1(a1);
        __syncwarp();

        if (lane < 3) {
            float o = l2b[lane];
            for (int cc = 0; cc < 64; cc++) o += tbuf[cc] * l2w[cc * 3 + lane];
            out[b * 3 + lane] = o;
        }
    }
}

// ------------------------- launch -------------------------
extern "C" void kernel_launch(void* const* d_in, const int* in_sizes, int n_in,
                              void* d_out, int out_size)
{
    const float* x      = (const float*)d_in[0];
    const int*   ei     = (const int*)  d_in[1];
    const float* eattr  = (const float*)d_in[2];
    const int*   batch  = (const int*)  d_in[3];
    const float* ee_w1  = (const float*)d_in[4];
    const float* ee_b1  = (const float*)d_in[5];
    const float* ee_w2  = (const float*)d_in[6];
    const float* ee_b2  = (const float*)d_in[7];
    const float* W1     = (const float*)d_in[8];
    const float* Ws     = (const float*)d_in[9];
    const float* att_s  = (const float*)d_in[10];
    const float* att_d  = (const float*)d_in[11];
    const float* We     = (const float*)d_in[12];
    const float* att_e  = (const float*)d_in[13];
    const float* bias   = (const float*)d_in[14];
    const float* lng    = (const float*)d_in[15];
    const float* lnb    = (const float*)d_in[16];
    const float* l1w    = (const float*)d_in[17];
    const float* l1b    = (const float*)d_in[18];
    const float* l2w    = (const float*)d_in[19];
    const float* l2b    = (const float*)d_in[20];
    float* out = (float*)d_out;

    const int* src = ei;
    const int* dst = ei + EE;

    k_prep_edge<<<PREPB + EDGE_BLOCKS, 256>>>(x, W1, Ws, att_s, att_d, We, att_e,
                                              eattr, dst, ee_w1, ee_b1, ee_w2, ee_b2);
    k_scan12<<<49, 1024>>>();
    k_scan3cs<<<49, 1024>>>();
    k_scatter<<<(EE / 4 + 255) / 256, 256>>>(src, dst);

    k_agg1<<<(NN + 7) / 8, 256>>>(x);
    k_fused12<<<(NN + 31) / 32, 256>>>(W1, bias, Ws);
    k_agg2<<<(NN + 7) / 8, 256>>>(bias + 64);

    k_final3<<<BB, 128>>>(batch, Ws + 16384, bias + 128,
                          lng, lnb, l1w, l1b, l2w, l2b, out);
}

// round 15
// speedup vs baseline: 1.0522x; 1.0522x over previous
#include <cuda_runtime.h>
#include <cuda_fp16.h>
#include <cstddef>

#define NN 50000
#define EE 800000
#define ET (EE + NN)
#define BB 50
#define FIN 16
#define HIDC 64
#define EDGE_BLOCKS ((EE + 255) / 256)
#define PREPB 196

// ------------------------- device scratch (static, zero-initialized at load) -------------------------
__device__ float  g_ew[EE];
__device__ int    g_erank[EE];        // edge rank within dst segment (histogram atomic return)
__device__ float  g_ewpart[EDGE_BLOCKS];
__device__ float  g_ew_mean;
__device__ int    g_deg[NN];          // zero at load; re-zeroed by k_scan3cs each run
__device__ int    g_off[NN + 1];
__device__ int    g_bsum[64];
__device__ int2   g_csr[ET];          // (src, ew bits)
__device__ float  g_y[(size_t)NN * 64];
__device__ __half g_h[(size_t)NN * 256];
__device__ float  g_x0[NN * HIDC];
__device__ float  g_x1[NN * HIDC];
__device__ float  g_as[NN * 4];
__device__ float  g_ad[NN * 4];
__device__ float  g_vs2[256], g_vd2[256], g_vs3[256], g_vd3[256];
__device__ float  g_ce[12];

__device__ __forceinline__ float elu1(float x)  { return x > 0.f ? x : __expf(x) - 1.f; }
__device__ __forceinline__ float lrelu(float x) { return x > 0.f ? x : 0.2f * x; }

// ------------------------- fused: prep (blocks 0..195) + edge MLP/histogram+rank (rest) -------------------------
__global__ void __launch_bounds__(256) k_prep_edge(
    const float* __restrict__ x, const float* __restrict__ W1, const float* __restrict__ Ws,
    const float* __restrict__ att_s, const float* __restrict__ att_d,
    const float* __restrict__ We, const float* __restrict__ att_e,
    const float* __restrict__ ea, const int* __restrict__ dst,
    const float* __restrict__ w1, const float* __restrict__ b1,
    const float* __restrict__ w2, const float* __restrict__ b2)
{
    int t = threadIdx.x;
    if (blockIdx.x < PREPB) {
        // ---- node prep: conv1 alphas + fold vectors ----
        __shared__ float svs[64], svd[64];
        if (t < 64) {
            int k = t >> 2, h = t & 3;
            float s = 0.f;
            for (int c = 0; c < 64; c++) s += W1[k * 256 + h * 64 + c] * att_s[h * 64 + c];
            svs[t] = s;
        } else if (t < 128) {
            int u = t - 64;
            int k = u >> 2, h = u & 3;
            float d = 0.f;
            for (int c = 0; c < 64; c++) d += W1[k * 256 + h * 64 + c] * att_d[h * 64 + c];
            svd[u] = d;
        }
        __syncthreads();

        int node = blockIdx.x * 256 + t;
        if (node < NN) {
            float xr[16];
            const float4* xp = (const float4*)(x + node * 16);
            #pragma unroll
            for (int q = 0; q < 4; q++) {
                float4 v = xp[q];
                xr[4*q] = v.x; xr[4*q+1] = v.y; xr[4*q+2] = v.z; xr[4*q+3] = v.w;
            }
            #pragma unroll
            for (int h = 0; h < 4; h++) {
                float a = 0.f, d = 0.f;
                #pragma unroll
                for (int k = 0; k < 16; k++) {
                    a += xr[k] * svs[k * 4 + h];
                    d += xr[k] * svd[k * 4 + h];
                }
                g_as[node * 4 + h] = a;
                g_ad[node * 4 + h] = d;
            }
        }

        if (blockIdx.x == 0) {
            int k = t >> 2, h = t & 3;
            float s2 = 0.f, d2 = 0.f, s3 = 0.f, d3 = 0.f;
            for (int c = 0; c < 64; c++) {
                float w2v = Ws[k * 256 + h * 64 + c];
                float w3v = Ws[16384 + k * 256 + h * 64 + c];
                s2 += w2v * att_s[256 + h * 64 + c];
                d2 += w2v * att_d[256 + h * 64 + c];
                s3 += w3v * att_s[512 + h * 64 + c];
                d3 += w3v * att_d[512 + h * 64 + c];
            }
            g_vs2[t] = s2; g_vd2[t] = d2; g_vs3[t] = s3; g_vd3[t] = d3;
            if (t < 12) {
                int l = t >> 2, hh = t & 3;
                float ce = 0.f;
                for (int c = 0; c < 64; c++) ce += We[l * 256 + hh * 64 + c] * att_e[l * 256 + hh * 64 + c];
                g_ce[t] = ce;
            }
        }
    } else {
        // ---- edge MLP + dst histogram (g_deg zero at kernel entry; atomic return = slot rank) ----
        __shared__ float ws[448];
        __shared__ float red[8];
        int eb = blockIdx.x - PREPB;
        for (int i = t; i < 448; i += 256)
            ws[i] = (i < 320) ? w1[i] : (i < 384) ? b1[i - 320] : w2[i - 384];
        __syncthreads();

        int e = eb * 256 + t;
        float val = 0.f;
        if (e < EE) {
            float a0 = ea[e*5+0], a1 = ea[e*5+1], a2 = ea[e*5+2], a3 = ea[e*5+3], a4 = ea[e*5+4];
            float acc = __ldg(b2);
            #pragma unroll 8
            for (int j = 0; j < 64; j++) {
                float tv = ws[320+j] + a0*ws[j] + a1*ws[64+j] + a2*ws[128+j] + a3*ws[192+j] + a4*ws[256+j];
                tv = fmaxf(tv, 0.f);
                acc += tv * ws[384+j];
            }
            val = 1.f / (1.f + __expf(-acc));
            g_ew[e] = val;
            g_erank[e] = atomicAdd(&g_deg[dst[e]], 1);
        }
        float s = val;
        #pragma unroll
        for (int o = 16; o; o >>= 1) s += __shfl_xor_sync(0xffffffffu, s, o);
        if ((t & 31) == 0) red[t >> 5] = s;
        __syncthreads();
        if (t == 0) {
            float tv = 0.f;
            for (int w = 0; w < 8; w++) tv += red[w];
            g_ewpart[eb] = tv;
        }
    }
}

// ------------------------- scan stage 1: per-block inclusive scan of deg+1 -------------------------
__global__ void k_scan1() {
    __shared__ int wsum[32];
    int tid = threadIdx.x, lane = tid & 31, w = tid >> 5;
    int i = blockIdx.x * 1024 + tid;
    int x = (i < NN) ? g_deg[i] + 1 : 0;
    #pragma unroll
    for (int d = 1; d < 32; d <<= 1) {
        int y = __shfl_up_sync(0xffffffffu, x, d);
        if (lane >= d) x += y;
    }
    if (lane == 31) wsum[w] = x;
    __syncthreads();
    if (w == 0) {
        int y = wsum[lane];
        #pragma unroll
        for (int d = 1; d < 32; d <<= 1) {
            int z = __shfl_up_sync(0xffffffffu, y, d);
            if (lane >= d) y += z;
        }
        wsum[lane] = y;
    }
    __syncthreads();
    if (w) x += wsum[w - 1];
    if (i < NN) g_off[i + 1] = x;
    if (tid == 1023) g_bsum[blockIdx.x] = x;
}

// ------------------------- scan stage 2 + edge-weight mean (one block) -------------------------
__global__ void __launch_bounds__(1024) k_scan2ew() {
    __shared__ float red[32];
    __shared__ int bs[64];
    int tid = threadIdx.x, lane = tid & 31;
    float s = 0.f;
    for (int i = tid; i < EDGE_BLOCKS; i += 1024) s += g_ewpart[i];
    #pragma unroll
    for (int o = 16; o; o >>= 1) s += __shfl_xor_sync(0xffffffffu, s, o);
    if (lane == 0) red[tid >> 5] = s;
    if (tid < 49) bs[tid] = g_bsum[tid];
    __syncthreads();
    if (tid == 0) {
        float tot = 0.f;
        for (int q = 0; q < 32; q++) tot += red[q];
        g_ew_mean = tot * (1.f / EE);
        int running = 0;
        for (int b = 0; b < 49; b++) { int t = bs[b]; bs[b] = running; running += t; }
    }
    __syncthreads();
    if (tid < 49) g_bsum[tid] = bs[tid];
}

// ------------------------- scan stage 3 + self-loop + deg re-zero -------------------------
__global__ void k_scan3cs() {
    int i = blockIdx.x * 1024 + threadIdx.x;
    if (i < NN) {
        int v = g_off[i + 1] + g_bsum[blockIdx.x];
        g_off[i + 1] = v;
        g_csr[v - 1] = make_int2(i, __float_as_int(g_ew_mean));
        g_deg[i] = 0;                            // ready for next replay
    }
    if (i == 0) g_off[0] = 0;
}

// ------------------------- scatter edges into CSR: NO atomics (rank precomputed), 4 edges/thread -------------------------
__global__ void __launch_bounds__(256) k_scatter(const int* __restrict__ src, const int* __restrict__ dst)
{
    int i4 = blockIdx.x * 256 + threadIdx.x;
    if (i4 >= EE / 4) return;    // EE % 4 == 0
    int4   d4 = ((const int4*)dst)[i4];
    int4   s4 = ((const int4*)src)[i4];
    int4   r4 = ((const int4*)g_erank)[i4];
    float4 w4 = ((const float4*)g_ew)[i4];
    int p0 = g_off[d4.x] + r4.x;
    int p1 = g_off[d4.y] + r4.y;
    int p2 = g_off[d4.z] + r4.z;
    int p3 = g_off[d4.w] + r4.w;
    g_csr[p0] = make_int2(s4.x, __float_as_int(w4.x));
    g_csr[p1] = make_int2(s4.y, __float_as_int(w4.y));
    g_csr[p2] = make_int2(s4.z, __float_as_int(w4.z));
    g_csr[p3] = make_int2(s4.w, __float_as_int(w4.w));
}

// ------------------------- conv1 aggregation (64 B/edge raw-x gather, MLP=4 pipeline) -------------------------
__global__ void __launch_bounds__(256) k_agg1(const float* __restrict__ x)
{
    __shared__ int   s_sm[8][32];
    __shared__ float4 p_sm[8][32];
    const unsigned F = 0xffffffffu;
    int lane = threadIdx.x & 31, w = threadIdx.x >> 5;
    int n = blockIdx.x * 8 + w;
    if (n >= NN) return;

    int start = g_off[n], end = g_off[n + 1];
    float4 adv = *(const float4*)(g_ad + n * 4);
    float ce0 = g_ce[0], ce1 = g_ce[1], ce2 = g_ce[2], ce3 = g_ce[3];
    int head = lane >> 3, kg = lane & 7;

    float a0 = 0.f, a1 = 0.f;
    float sl0 = 0.f, sl1 = 0.f, sl2 = 0.f, sl3 = 0.f;
    const float* pr = (const float*)(p_sm[w]);
    const int* sr = s_sm[w];

    for (int base = start; base < end; base += 32) {
        int i = base + lane;
        bool v = i < end;
        int2 ed = v ? g_csr[i] : make_int2(0, 0);
        int sidx = ed.x;
        float wgt = __int_as_float(ed.y);
        float4 asv = *(const float4*)(g_as + sidx * 4);
        float p0 = v ? __expf(lrelu(asv.x + adv.x + wgt * ce0)) : 0.f;
        float p1 = v ? __expf(lrelu(asv.y + adv.y + wgt * ce1)) : 0.f;
        float p2 = v ? __expf(lrelu(asv.z + adv.z + wgt * ce2)) : 0.f;
        float p3 = v ? __expf(lrelu(asv.w + adv.w + wgt * ce3)) : 0.f;
        sl0 += p0; sl1 += p1; sl2 += p2; sl3 += p3;
        s_sm[w][lane] = sidx;
        p_sm[w][lane] = make_float4(p0, p1, p2, p3);
        __syncwarp();
        int cnt4 = (min(32, end - base) + 3) & ~3;   // padded slots carry p=0 -> contribute 0
        for (int kk = 0; kk < cnt4; kk += 4) {
            int s0 = sr[kk], s1 = sr[kk+1], s2 = sr[kk+2], s3 = sr[kk+3];
            float2 xa = *(const float2*)(x + s0 * 16 + kg * 2);
            float2 xb = *(const float2*)(x + s1 * 16 + kg * 2);
            float2 xc = *(const float2*)(x + s2 * 16 + kg * 2);
            float2 xd = *(const float2*)(x + s3 * 16 + kg * 2);
            float pk0 = pr[kk*4+head], pk1 = pr[(kk+1)*4+head];
            float pk2 = pr[(kk+2)*4+head], pk3 = pr[(kk+3)*4+head];
            a0 += pk0 * xa.x; a1 += pk0 * xa.y;
            a0 += pk1 * xb.x; a1 += pk1 * xb.y;
            a0 += pk2 * xc.x; a1 += pk2 * xc.y;
            a0 += pk3 * xd.x; a1 += pk3 * xd.y;
        }
        __syncwarp();
    }

    #pragma unroll
    for (int o = 16; o; o >>= 1) {
        sl0 += __shfl_xor_sync(F, sl0, o);
        sl1 += __shfl_xor_sync(F, sl1, o);
        sl2 += __shfl_xor_sync(F, sl2, o);
        sl3 += __shfl_xor_sync(F, sl3, o);
    }
    float myS = (lane & 16) ? ((lane & 8) ? sl3 : sl2) : ((lane & 8) ? sl1 : sl0);
    float inv = 1.f / (myS + 1e-16f);
    *(float2*)(g_y + (size_t)n * 64 + head * 16 + kg * 2) = make_float2(a0 * inv, a1 * inv);
}

// ------------------------- fused conv1-post + conv2-GEMM + conv2 alphas -------------------------
__global__ void __launch_bounds__(256) k_fused12(
    const float* __restrict__ W1, const float* __restrict__ bias1, const float* __restrict__ Ws)
{
    __shared__ __align__(16) float ys[32 * 64];
    __shared__ __align__(16) float xs[32 * 64];
    int t = threadIdx.x;
    int n0 = blockIdx.x * 32;

    for (int i = t; i < 32 * 64; i += 256) {
        int gi = n0 * 64 + i;
        ys[i] = (gi < NN * 64) ? g_y[gi] : 0.f;
    }
    __syncthreads();

    // Phase A: x0 = elu(Y1 @ W1fold + b) -> xs + g_x0
    {
        int c = t & 63, grp = t >> 6;
        unsigned long long wd[32];
        #pragma unroll
        for (int j2 = 0; j2 < 32; j2++) {
            int j = 2 * j2;
            int k = j & 15, hh = j >> 4;
            float w0 = W1[k * 256 + hh * 64 + c] * 0.25f;
            float w1v = W1[(k + 1) * 256 + hh * 64 + c] * 0.25f;
            asm("mov.b64 %0, {%1, %2};" : "=l"(wd[j2]) : "f"(w0), "f"(w1v));
        }
        float bc = bias1[c];
        for (int nn = grp * 8; nn < grp * 8 + 8; nn++) {
            int node = n0 + nn;
            const ulonglong2* y2 = (const ulonglong2*)(ys + nn * 64);
            unsigned long long acc = 0ull;
            #pragma unroll
            for (int q = 0; q < 16; q++) {
                ulonglong2 v = y2[q];
                asm("fma.rn.f32x2 %0, %1, %2, %0;" : "+l"(acc) : "l"(v.x), "l"(wd[2 * q]));
                asm("fma.rn.f32x2 %0, %1, %2, %0;" : "+l"(acc) : "l"(v.y), "l"(wd[2 * q + 1]));
            }
            float lo, hi;
            asm("mov.b64 {%0, %1}, %2;" : "=f"(lo), "=f"(hi) : "l"(acc));
            float val = elu1(lo + hi + bc);
            xs[nn * 64 + c] = val;
            if (node < NN) g_x0[node * 64 + c] = val;
        }
    }
    __syncthreads();

    // Phase B: h2 = x0 @ W2 (fp16 out)
    {
        unsigned long long wd[32];
        #pragma unroll
        for (int k2 = 0; k2 < 32; k2++) {
            float w0 = Ws[(2 * k2) * 256 + t];
            float w1v = Ws[(2 * k2 + 1) * 256 + t];
            asm("mov.b64 %0, {%1, %2};" : "=l"(wd[k2]) : "f"(w0), "f"(w1v));
        }
        for (int nn = 0; nn < 32; nn++) {
            int node = n0 + nn;
            if (node >= NN) break;
            const ulonglong2* x2 = (const ulonglong2*)(xs + nn * 64);
            unsigned long long acc = 0ull;
            #pragma unroll
            for (int q = 0; q < 16; q++) {
                ulonglong2 v = x2[q];
                asm("fma.rn.f32x2 %0, %1, %2, %0;" : "+l"(acc) : "l"(v.x), "l"(wd[2 * q]));
                asm("fma.rn.f32x2 %0, %1, %2, %0;" : "+l"(acc) : "l"(v.y), "l"(wd[2 * q + 1]));
            }
            float lo, hi;
            asm("mov.b64 {%0, %1}, %2;" : "=f"(lo), "=f"(hi) : "l"(acc));
            g_h[(size_t)node * 256 + t] = __float2half(lo + hi);
        }
    }

    // Phase C: conv2 attention dots (256 slots = 32 nodes x 8 roles)
    {
        int nn = t >> 3, role = t & 7, h = role & 3;
        int node = n0 + nn;
        if (node < NN) {
            const float* vv = (role < 4) ? g_vs2 : g_vd2;
            float a = 0.f;
            #pragma unroll
            for (int k = 0; k < 64; k++) a += xs[nn * 64 + k] * vv[k * 4 + h];
            ((role < 4) ? g_as : g_ad)[node * 4 + h] = a;
        }
    }
}

// ------------------------- conv2 aggregation (512 B/edge fp16 h gather, MLP=4) + residual epilogue -------------------------
__global__ void __launch_bounds__(256) k_agg2(const float* __restrict__ bias)
{
    __shared__ int   s_sm[8][32];
    __shared__ float4 p_sm[8][32];
    const unsigned F = 0xffffffffu;
    int lane = threadIdx.x & 31, w = threadIdx.x >> 5;
    int n = blockIdx.x * 8 + w;
    if (n >= NN) return;

    int start = g_off[n], end = g_off[n + 1];
    float4 adv = *(const float4*)(g_ad + n * 4);
    float ce0 = g_ce[4], ce1 = g_ce[5], ce2 = g_ce[6], ce3 = g_ce[7];
    int head = lane >> 3;

    float sl0 = 0.f, sl1 = 0.f, sl2 = 0.f, sl3 = 0.f;
    float acc[8];
    #pragma unroll
    for (int j = 0; j < 8; j++) acc[j] = 0.f;
    const float* pr = (const float*)(p_sm[w]);
    const int* sr = s_sm[w];

    for (int base = start; base < end; base += 32) {
        int i = base + lane;
        bool v = i < end;
        int2 ed = v ? g_csr[i] : make_int2(0, 0);
        int sidx = ed.x;
        float wgt = __int_as_float(ed.y);
        float4 asv = *(const float4*)(g_as + sidx * 4);
        float p0 = v ? __expf(lrelu(asv.x + adv.x + wgt * ce0)) : 0.f;
        float p1 = v ? __expf(lrelu(asv.y + adv.y + wgt * ce1)) : 0.f;
        float p2 = v ? __expf(lrelu(asv.z + adv.z + wgt * ce2)) : 0.f;
        float p3 = v ? __expf(lrelu(asv.w + adv.w + wgt * ce3)) : 0.f;
        sl0 += p0; sl1 += p1; sl2 += p2; sl3 += p3;
        s_sm[w][lane] = sidx;
        p_sm[w][lane] = make_float4(p0, p1, p2, p3);
        __syncwarp();
        int cnt4 = (min(32, end - base) + 3) & ~3;   // padded slots carry p=0
        for (int kk = 0; kk < cnt4; kk += 4) {
            int s0 = sr[kk], s1 = sr[kk+1], s2 = sr[kk+2], s3 = sr[kk+3];
            uint4 h0 = *(const uint4*)(g_h + ((size_t)s0 << 8) + (lane << 3));
            uint4 h1 = *(const uint4*)(g_h + ((size_t)s1 << 8) + (lane << 3));
            uint4 h2 = *(const uint4*)(g_h + ((size_t)s2 << 8) + (lane << 3));
            uint4 h3 = *(const uint4*)(g_h + ((size_t)s3 << 8) + (lane << 3));
            float pk0 = pr[kk*4+head], pk1 = pr[(kk+1)*4+head];
            float pk2 = pr[(kk+2)*4+head], pk3 = pr[(kk+3)*4+head];
            #pragma unroll
            for (int q = 0; q < 4; q++) {
                float2 f0 = __half22float2(*reinterpret_cast<__half2*>(&(&h0.x)[q]));
                float2 f1 = __half22float2(*reinterpret_cast<__half2*>(&(&h1.x)[q]));
                float2 f2 = __half22float2(*reinterpret_cast<__half2*>(&(&h2.x)[q]));
                float2 f3 = __half22float2(*reinterpret_cast<__half2*>(&(&h3.x)[q]));
                acc[2*q]   += pk0 * f0.x + pk1 * f1.x + pk2 * f2.x + pk3 * f3.x;
                acc[2*q+1] += pk0 * f0.y + pk1 * f1.y + pk2 * f2.y + pk3 * f3.y;
            }
        }
        __syncwarp();
    }

    #pragma unroll
    for (int o = 16; o; o >>= 1) {
        sl0 += __shfl_xor_sync(F, sl0, o);
        sl1 += __shfl_xor_sync(F, sl1, o);
        sl2 += __shfl_xor_sync(F, sl2, o);
        sl3 += __shfl_xor_sync(F, sl3, o);
    }
    float myS = (lane & 16) ? ((lane & 8) ? sl3 : sl2) : ((lane & 8) ? sl1 : sl0);
    float inv = 1.f / (myS + 1e-16f);
    float r[8];
    #pragma unroll
    for (int j = 0; j < 8; j++) {
        float vv = acc[j] * inv;
        vv += __shfl_xor_sync(F, vv, 8);
        vv += __shfl_xor_sync(F, vv, 16);
        r[j] = vv;
    }
    if (lane < 8) {
        float o[8];
        #pragma unroll
        for (int j = 0; j < 8; j++) {
            int c = lane * 8 + j;
            o[j] = elu1(0.25f * r[j] + __ldg(bias + c) + g_x0[(size_t)n * 64 + c]);
        }
        float4* op = (float4*)(g_x1 + (size_t)n * 64 + lane * 8);
        op[0] = make_float4(o[0], o[1], o[2], o[3]);
        op[1] = make_float4(o[4], o[5], o[6], o[7]);
    }
}

// ------------------------- conv3 @ 50 targets + LayerNorm + MLP -------------------------
__global__ void __launch_bounds__(128) k_final3(
    const int* __restrict__ batch, const float* __restrict__ Ws3, const float* __restrict__ bias3,
    const float* __restrict__ lng, const float* __restrict__ lnb,
    const float* __restrict__ l1w, const float* __restrict__ l1b,
    const float* __restrict__ l2w, const float* __restrict__ l2b,
    float* __restrict__ out)
{
    __shared__ float xnode[64];
    __shared__ float adsh[4];
    __shared__ float ysh[4][4][64];
    __shared__ float ssh[4][4];
    __shared__ float Y[4][64];
    __shared__ float pt[128];
    __shared__ float xbuf[64], tbuf[64];
    const unsigned F = 0xffffffffu;
    int t = threadIdx.x, lane = t & 31, w = t >> 5;
    int b = blockIdx.x;

    int lo = 0, hi = NN;
    while (lo < hi) {
        int mid = (lo + hi) >> 1;
        if (batch[mid] < b) lo = mid + 1; else hi = mid;
    }
    int n = lo;

    if (t < 64) xnode[t] = g_x1[(size_t)n * 64 + t];
    __syncthreads();
    if (t < 4) {
        float a = 0.f;
        #pragma unroll
        for (int k = 0; k < 64; k++) a += xnode[k] * g_vd3[k * 4 + t];
        adsh[t] = a;
    }
    __syncthreads();

    float4 adv = make_float4(adsh[0], adsh[1], adsh[2], adsh[3]);
    float ce0 = g_ce[8], ce1 = g_ce[9], ce2 = g_ce[10], ce3 = g_ce[11];
    int start = g_off[n], len = g_off[n + 1] - start;

    float4 v0 = *(const float4*)(g_vs3 + lane * 8);
    float4 v1 = *(const float4*)(g_vs3 + lane * 8 + 4);

    float yk[8];
    #pragma unroll
    for (int j = 0; j < 8; j++) yk[j] = 0.f;
    float sw0 = 0.f, sw1 = 0.f, sw2 = 0.f, sw3 = 0.f;

    for (int j = w; j < len; j += 4) {
        int2 ed = g_csr[start + j];
        int s = ed.x;
        float wgt = __int_as_float(ed.y);
        float2 xs = *(const float2*)(g_x1 + (size_t)s * 64 + lane * 2);
        float d0 = xs.x * v0.x + xs.y * v1.x;
        float d1 = xs.x * v0.y + xs.y * v1.y;
        float d2 = xs.x * v0.z + xs.y * v1.z;
        float d3 = xs.x * v0.w + xs.y * v1.w;
        #pragma unroll
        for (int o = 16; o; o >>= 1) {
            d0 += __shfl_xor_sync(F, d0, o);
            d1 += __shfl_xor_sync(F, d1, o);
            d2 += __shfl_xor_sync(F, d2, o);
            d3 += __shfl_xor_sync(F, d3, o);
        }
        float p0 = __expf(lrelu(d0 + adv.x + wgt * ce0));
        float p1 = __expf(lrelu(d1 + adv.y + wgt * ce1));
        float p2 = __expf(lrelu(d2 + adv.z + wgt * ce2));
        float p3 = __expf(lrelu(d3 + adv.w + wgt * ce3));
        sw0 += p0; sw1 += p1; sw2 += p2; sw3 += p3;
        yk[0] += p0 * xs.x; yk[1] += p0 * xs.y;
        yk[2] += p1 * xs.x; yk[3] += p1 * xs.y;
        yk[4] += p2 * xs.x; yk[5] += p2 * xs.y;
        yk[6] += p3 * xs.x; yk[7] += p3 * xs.y;
    }
    #pragma unroll
    for (int h = 0; h < 4; h++) {
        ysh[w][h][lane * 2]     = yk[h * 2];
        ysh[w][h][lane * 2 + 1] = yk[h * 2 + 1];
    }
    if (lane == 0) { ssh[w][0] = sw0; ssh[w][1] = sw1; ssh[w][2] = sw2; ssh[w][3] = sw3; }
    __syncthreads();

    #pragma unroll
    for (int r = 0; r < 2; r++) {
        int idx = t + r * 128;
        int h = idx >> 6, k = idx & 63;
        float v = ysh[0][h][k] + ysh[1][h][k] + ysh[2][h][k] + ysh[3][h][k];
        float sh = ssh[0][h] + ssh[1][h] + ssh[2][h] + ssh[3][h];
        Y[h][k] = v / (sh + 1e-16f);
    }
    __syncthreads();

    int c = t & 63, half = t >> 6;
    float a = 0.f;
    #pragma unroll
    for (int hh = 0; hh < 2; hh++) {
        int h = half * 2 + hh;
        for (int k = 0; k < 64; k++) a += Y[h][k] * __ldg(Ws3 + k * 256 + h * 64 + c);
    }
    pt[t] = a;
    __syncthreads();
    if (t < 64) xbuf[t] = elu1(0.25f * (pt[t] + pt[t + 64]) + bias3[t] + xnode[t]);
    __syncthreads();

    if (w == 0) {
        float v0l = xbuf[lane], v1l = xbuf[lane + 32];
        float sum = v0l + v1l;
        #pragma unroll
        for (int o = 16; o; o >>= 1) sum += __shfl_xor_sync(F, sum, o);
        float mean = sum * (1.f / 64.f);
        float dd0 = v0l - mean, dd1 = v1l - mean;
        float vs = dd0 * dd0 + dd1 * dd1;
        #pragma unroll
        for (int o = 16; o; o >>= 1) vs += __shfl_xor_sync(F, vs, o);
        float rstd = rsqrtf(vs * (1.f / 64.f) + 1e-5f);
        xbuf[lane]      = dd0 * rstd * lng[lane]      + lnb[lane];
        xbuf[lane + 32] = dd1 * rstd * lng[lane + 32] + lnb[lane + 32];
        __syncwarp();

        float a0 = l1b[lane], a1 = l1b[lane + 32];
        for (int cc = 0; cc < 64; cc++) {
            float xv = xbuf[cc];
            a0 += xv * l1w[cc * 64 + lane];
            a1 += xv * l1w[cc * 64 + lane + 32];
        }
        tbuf[lane]      = elu1(a0);
        tbuf[lane + 32] = elu1(a1);
        __syncwarp();

        if (lane < 3) {
            float o = l2b[lane];
            for (int cc = 0; cc < 64; cc++) o += tbuf[cc] * l2w[cc * 3 + lane];
            out[b * 3 + lane] = o;
        }
    }
}

// ------------------------- launch -------------------------
extern "C" void kernel_launch(void* const* d_in, const int* in_sizes, int n_in,
                              void* d_out, int out_size)
{
    const float* x      = (const float*)d_in[0];
    const int*   ei     = (const int*)  d_in[1];
    const float* eattr  = (const float*)d_in[2];
    const int*   batch  = (const int*)  d_in[3];
    const float* ee_w1  = (const float*)d_in[4];
    const float* ee_b1  = (const float*)d_in[5];
    const float* ee_w2  = (const float*)d_in[6];
    const float* ee_b2  = (const float*)d_in[7];
    const float* W1     = (const float*)d_in[8];
    const float* Ws     = (const float*)d_in[9];
    const float* att_s  = (const float*)d_in[10];
    const float* att_d  = (const float*)d_in[11];
    const float* We     = (const float*)d_in[12];
    const float* att_e  = (const float*)d_in[13];
    const float* bias   = (const float*)d_in[14];
    const float* lng    = (const float*)d_in[15];
    const float* lnb    = (const float*)d_in[16];
    const float* l1w    = (const float*)d_in[17];
    const float* l1b    = (const float*)d_in[18];
    const float* l2w    = (const float*)d_in[19];
    const float* l2b    = (const float*)d_in[20];
    float* out = (float*)d_out;

    const int* src = ei;
    const int* dst = ei + EE;

    k_prep_edge<<<PREPB + EDGE_BLOCKS, 256>>>(x, W1, Ws, att_s, att_d, We, att_e,
                                              eattr, dst, ee_w1, ee_b1, ee_w2, ee_b2);
    k_scan1<<<49, 1024>>>();
    k_scan2ew<<<1, 1024>>>();
    k_scan3cs<<<49, 1024>>>();
    k_scatter<<<(EE / 4 + 255) / 256, 256>>>(src, dst);

    k_agg1<<<(NN + 7) / 8, 256>>>(x);
    k_fused12<<<(NN + 31) / 32, 256>>>(W1, bias, Ws);
    k_agg2<<<(NN + 7) / 8, 256>>>(bias + 64);

    k_final3<<<BB, 128>>>(batch, Ws + 16384, bias + 128,
                          lng, lnb, l1w, l1b, l2w, l2b, out);
}